// round 14
// baseline (speedup 1.0000x reference)
#include <cuda_runtime.h>
#include <cstdint>

#define EMBED 1024
#define HEAD  128
#define SEQ   4096
#define BATCH 4
#define ROWS_TOTAL (BATCH*SEQ)

typedef unsigned long long u64;
typedef unsigned int u32;

// scratch (device globals; no allocations allowed)
static __device__ float g_q [(size_t)ROWS_TOTAL * HEAD];    // fp32, [b][s][h'] h-interleaved
static __device__ float g_k [(size_t)ROWS_TOTAL * HEAD];    // tf32 BITS, [b][s][h'] h-interleaved
static __device__ float g_vT[(size_t)BATCH * HEAD * SEQ];   // tf32 BITS, [b][h][s'] s-interleaved
static __device__ float g_part[(size_t)2 * ROWS_TOTAL * HEAD];
static __device__ float g_mp[2 * ROWS_TOTAL];
static __device__ float g_lp[2 * ROWS_TOTAL];

__device__ __forceinline__ u64 pack2(float lo, float hi) {
    u64 r; asm("mov.b64 %0, {%1, %2};" : "=l"(r) : "f"(lo), "f"(hi)); return r;
}
__device__ __forceinline__ void unpk(u64 v, u32& lo, u32& hi) {
    asm("mov.b64 {%0, %1}, %2;" : "=r"(lo), "=r"(hi) : "l"(v));
}
__device__ __forceinline__ u32 tf32_rna(float f) {
    u32 r; asm("cvt.rna.tf32.f32 %0, %1;" : "=r"(r) : "f"(f)); return r;
}
__device__ __forceinline__ int p8(int j) { return (j < 4) ? (j << 1) : (((j - 4) << 1) | 1); }
__device__ __forceinline__ u32 smem_u32(const void* p) {
    u32 a; asm("{ .reg .u64 t; cvta.to.shared.u64 t, %1; cvt.u32.u64 %0, t; }" : "=r"(a) : "l"(p));
    return a;
}
#define CP16(dst_u32, src_ptr) \
    asm volatile("cp.async.cg.shared.global [%0], [%1], 16;" :: "r"(dst_u32), "l"(src_ptr))
#define CP_COMMIT() asm volatile("cp.async.commit_group;" ::: "memory")
#define CP_WAIT0()  asm volatile("cp.async.wait_group 0;" ::: "memory")

__device__ __forceinline__ void mma_tf32(float* d, u32 a0, u32 a1, u32 a2, u32 a3,
                                         u32 b0, u32 b1) {
    asm volatile("mma.sync.aligned.m16n8k8.row.col.f32.tf32.tf32.f32 "
        "{%0,%1,%2,%3}, {%4,%5,%6,%7}, {%8,%9}, {%0,%1,%2,%3};"
        : "+f"(d[0]), "+f"(d[1]), "+f"(d[2]), "+f"(d[3])
        : "r"(a0), "r"(a1), "r"(a2), "r"(a3), "r"(b0), "r"(b1));
}

// ============================================================================
// Kernel 1: QKV via mma.sync tf32 (byte-identical to passing R13 version)
// ============================================================================
#define BM 128
#define BK 32
#define NCH (EMBED / BK)
#define AS_STR 36
#define BS_STR 136
#define AS_SZ (BM * AS_STR)
#define BS_SZ (BK * BS_STR)
#define QKV_SMEM ((AS_SZ + BS_SZ) * 2 * 4)

__global__ __launch_bounds__(256, 1) void qkv_mma_kernel(
    const float* __restrict__ x, const float* __restrict__ Wq,
    const float* __restrict__ Wk, const float* __restrict__ Wv)
{
    extern __shared__ __align__(16) float smq[];
    const int tid  = threadIdx.x;
    const int lane = tid & 31;
    const int wid  = tid >> 5;
    const int warp_m = (wid >> 2) * 64;
    const int warp_n = (wid & 3) * 32;
    const int m0 = blockIdx.x * BM;
    const int w  = blockIdx.y;
    const float* W = (w == 0) ? Wq : (w == 1) ? Wk : Wv;

    float* Asb[2] = { smq,         smq + AS_SZ + BS_SZ };
    float* Bsb[2] = { smq + AS_SZ, smq + 2 * AS_SZ + BS_SZ };

    float4 areg[4], breg[4];

#define LDG_CHUNK(c) do { \
    _Pragma("unroll") \
    for (int i = 0; i < 4; i++) { \
        int idx = tid + i * 256; \
        int row = idx >> 3, kq = idx & 7; \
        areg[i] = *(const float4*)(x + (size_t)(m0 + row) * EMBED + (c) * BK + kq * 4); \
        int k = idx >> 5, nq = idx & 31; \
        breg[i] = *(const float4*)(W + (size_t)((c) * BK + k) * HEAD + nq * 4); \
    } \
} while (0)

#define STS_CHUNK(buf) do { \
    _Pragma("unroll") \
    for (int i = 0; i < 4; i++) { \
        int idx = tid + i * 256; \
        int row = idx >> 3, kq = idx & 7; \
        uint4 av = { tf32_rna(areg[i].x), tf32_rna(areg[i].y), \
                     tf32_rna(areg[i].z), tf32_rna(areg[i].w) }; \
        *(uint4*)(Asb[buf] + row * AS_STR + kq * 4) = av; \
        int k = idx >> 5, nq = idx & 31; \
        uint4 bv = { tf32_rna(breg[i].x), tf32_rna(breg[i].y), \
                     tf32_rna(breg[i].z), tf32_rna(breg[i].w) }; \
        *(uint4*)(Bsb[buf] + k * BS_STR + nq * 4) = bv; \
    } \
} while (0)

    float acc[4][4][4];
#pragma unroll
    for (int mf = 0; mf < 4; mf++)
#pragma unroll
        for (int nf = 0; nf < 4; nf++)
#pragma unroll
            for (int i = 0; i < 4; i++) acc[mf][nf][i] = 0.0f;

    LDG_CHUNK(0);
    STS_CHUNK(0);
    __syncthreads();

    for (int c = 0; c < NCH; c++) {
        const int buf = c & 1;
        if (c + 1 < NCH) LDG_CHUNK(c + 1);

        const u32* ap = (const u32*)Asb[buf] + (warp_m + (lane >> 2)) * AS_STR + (lane & 3);
        const u32* bp = (const u32*)Bsb[buf] + (lane & 3) * BS_STR + warp_n + (lane >> 2);
#pragma unroll
        for (int ks = 0; ks < 4; ks++) {
            u32 a[4][4], b[4][2];
#pragma unroll
            for (int mf = 0; mf < 4; mf++) {
                const int o = mf * (16 * AS_STR) + ks * 8;
                a[mf][0] = ap[o];
                a[mf][1] = ap[o + 8 * AS_STR];
                a[mf][2] = ap[o + 4];
                a[mf][3] = ap[o + 8 * AS_STR + 4];
            }
#pragma unroll
            for (int nf = 0; nf < 4; nf++) {
                const int o = ks * (8 * BS_STR) + nf * 8;
                b[nf][0] = bp[o];
                b[nf][1] = bp[o + 4 * BS_STR];
            }
#pragma unroll
            for (int mf = 0; mf < 4; mf++)
#pragma unroll
                for (int nf = 0; nf < 4; nf++)
                    mma_tf32(acc[mf][nf], a[mf][0], a[mf][1], a[mf][2], a[mf][3],
                             b[nf][0], b[nf][1]);
        }

        if (c + 1 < NCH) {
            STS_CHUNK((c + 1) & 1);
            __syncthreads();
        }
    }

    const int lr = lane & 3;
    const int g0 = p8(2 * lr), g1 = p8(2 * lr + 1);
#pragma unroll
    for (int mf = 0; mf < 4; mf++) {
        const int mrow = m0 + warp_m + mf * 16 + (lane >> 2);
#pragma unroll
        for (int nf = 0; nf < 4; nf++) {
            const int nbase = warp_n + nf * 8;
            if (w == 2) {
                const int b0 = mrow >> 12, rb = mrow & (SEQ - 1);
                const int rbp = (rb & ~7) | p8(rb & 7);
                u32* vp = (u32*)(g_vT + ((size_t)b0 * HEAD + nbase + 2 * lr) * SEQ + rbp);
                vp[0]       = tf32_rna(acc[mf][nf][0]);
                vp[SEQ]     = tf32_rna(acc[mf][nf][1]);
                vp[8]       = tf32_rna(acc[mf][nf][2]);
                vp[SEQ + 8] = tf32_rna(acc[mf][nf][3]);
            } else if (w == 1) {
                u32* p0 = (u32*)(g_k + (size_t)mrow * HEAD + nbase);
                p0[g0]            = tf32_rna(acc[mf][nf][0]);
                p0[g1]            = tf32_rna(acc[mf][nf][1]);
                p0[g0 + 8 * HEAD] = tf32_rna(acc[mf][nf][2]);
                p0[g1 + 8 * HEAD] = tf32_rna(acc[mf][nf][3]);
            } else {
                float* p0 = g_q + (size_t)mrow * HEAD + nbase;
                p0[g0]            = acc[mf][nf][0];
                p0[g1]            = acc[mf][nf][1];
                p0[g0 + 8 * HEAD] = acc[mf][nf][2];
                p0[g1 + 8 * HEAD] = acc[mf][nf][3];
            }
        }
    }
#undef LDG_CHUNK
#undef STS_CHUNK
}

// ============================================================================
// Kernel 2: flash attention, 512 threads = 16 warps (4/SMSP).
// Warp (rowgrp = w&7, nh = w>>3): q-rows [16*rowgrp,+16), n-half nh.
// Scores m16 x n32/warp; AV m16 x n64/warp. Cross-half softmax via smem.
// K/V cp.async double-buffered; Q frags in regs.
// ============================================================================
#define NEG_BIG (-3.0e38f)
#define M_INIT  (-1.0e30f)
#define QT_STR 136
#define KS_STR 136
#define VS_STR 72
#define PS_STR 72
#define KS_SZ (64 * KS_STR)
#define VS_SZ (128 * VS_STR)
#define PS_SZ (128 * PS_STR)
#define RED_SZ 512                          // smax 2x128 + ssum 2x128
#define ATT_SMEM ((2 * (KS_SZ + VS_SZ) + PS_SZ + RED_SZ) * 4)   // 182272 B

__global__ __launch_bounds__(512, 1) void attn_kernel()
{
    extern __shared__ __align__(16) float smf[];
    float* Ks0 = smf;
    float* Vs0 = Ks0 + KS_SZ;
    float* Ks1 = Vs0 + VS_SZ;
    float* Vs1 = Ks1 + KS_SZ;
    float* Ps  = Vs1 + VS_SZ;
    float* smax = Ps + PS_SZ;        // [2][128]
    float* ssum = smax + 256;        // [2][128]
    float* Qtmp = Ks1;               // transient Q staging (128*136 fits K1+V1)

    const int tid  = threadIdx.x;
    const int lane = tid & 31;
    const int w    = tid >> 5;           // 0..15
    const int rowg = w & 7;
    const int nh   = w >> 3;             // n-half
    const int id = blockIdx.x;
    const int qt = 31 - (id >> 3);
    const int z  = id & 1;
    const int b  = (id >> 1) & 3;
    const int q0 = qt * 128;
    const float scale = 0.08838834764831845f;

    const int lq = lane >> 2;
    const int lr = lane & 3;
    const int rlo = rowg * 16 + lq, rhi = rlo + 8;
    const int g0 = p8(2 * lr), g1 = p8(2 * lr + 1);

    const int kt0 = z ? (qt + 1) : 0;
    const int kt1 = z ? (2 * qt + 2) : (qt + 1);

#define LOAD_TILE(ktv, Kd, Vd) do { \
    const float* kg = g_k + ((size_t)b * SEQ + (size_t)(ktv) * 64) * HEAD; \
    const float* vg = g_vT + (size_t)b * HEAD * SEQ + (size_t)(ktv) * 64; \
    _Pragma("unroll") \
    for (int i = 0; i < 4; i++) { \
        int idx = tid + i * 512; \
        int e4 = idx & 31, r = idx >> 5; \
        CP16(smem_u32((Kd) + r * KS_STR + e4 * 4), kg + (size_t)r * HEAD + e4 * 4); \
        int h = idx >> 4, k4 = idx & 15; \
        CP16(smem_u32((Vd) + h * VS_STR + k4 * 4), vg + (size_t)h * SEQ + k4 * 4); \
    } \
} while (0)

    // preload first K/V tile into stage 0 (overlaps Q setup in stage-1 region)
    LOAD_TILE(kt0, Ks0, Vs0);
    CP_COMMIT();

    // stage Q (scaled + rna) into transient smem
    {
        const float* qg = g_q + ((size_t)b * SEQ + q0) * HEAD;
#pragma unroll
        for (int i = 0; i < 8; i++) {
            int idx = tid + i * 512;
            int h4 = idx >> 7, r = idx & 127;
            float4 v = *(const float4*)(qg + (size_t)r * HEAD + h4 * 4);
            uint4 t = { tf32_rna(v.x * scale), tf32_rna(v.y * scale),
                        tf32_rna(v.z * scale), tf32_rna(v.w * scale) };
            *(uint4*)(Qtmp + r * QT_STR + h4 * 4) = t;
        }
    }
    __syncthreads();
    u32 qa[16][4];
    {
        const u32* apl = (const u32*)Qtmp + rlo * QT_STR + 2 * lr;
        const u32* aph = (const u32*)Qtmp + rhi * QT_STR + 2 * lr;
#pragma unroll
        for (int ks = 0; ks < 16; ks++) {
            unpk(*(const u64*)(apl + ks * 8), qa[ks][0], qa[ks][2]);
            unpk(*(const u64*)(aph + ks * 8), qa[ks][1], qa[ks][3]);
        }
    }
    CP_WAIT0();
    __syncthreads();

    float O[8][4];
#pragma unroll
    for (int nf = 0; nf < 8; nf++)
#pragma unroll
        for (int i = 0; i < 4; i++) O[nf][i] = 0.0f;
    float mlo = M_INIT, mhi = M_INIT, llo = 0.0f, lhi = 0.0f;

    for (int kt = kt0; kt < kt1; kt++) {
        const int st = (kt - kt0) & 1;
        float* Kc = st ? Ks1 : Ks0;
        float* Vc = st ? Vs1 : Vs0;

        if (kt + 1 < kt1) {
            LOAD_TILE(kt + 1, st ? Ks0 : Ks1, st ? Vs0 : Vs1);
            CP_COMMIT();
        }

        // ---- scores: m16 x n32 (warp's n-half) ----
        float acc[4][4];
#pragma unroll
        for (int nf = 0; nf < 4; nf++)
#pragma unroll
            for (int i = 0; i < 4; i++) acc[nf][i] = 0.0f;

        const u32* bp = (const u32*)Kc + lq * KS_STR + 2 * lr;
#pragma unroll 4
        for (int ks = 0; ks < 16; ks++) {
            const int ko = ks * 8;
#pragma unroll
            for (int nf = 0; nf < 4; nf++) {
                u32 b0, b1;
                unpk(*(const u64*)(bp + (nh * 4 + nf) * (8 * KS_STR) + ko), b0, b1);
                mma_tf32(acc[nf], qa[ks][0], qa[ks][1], qa[ks][2], qa[ks][3], b0, b1);
            }
        }

        if (kt >= 2 * qt) {
            const int koff = (kt - 2 * qt) * 64;
#pragma unroll
            for (int nf = 0; nf < 4; nf++) {
                const int c0 = koff + (nh * 4 + nf) * 8 + 2 * lr;
                if (c0 > rlo)     acc[nf][0] = NEG_BIG;
                if (c0 + 1 > rlo) acc[nf][1] = NEG_BIG;
                if (c0 > rhi)     acc[nf][2] = NEG_BIG;
                if (c0 + 1 > rhi) acc[nf][3] = NEG_BIG;
            }
        }

        // ---- softmax part 1: per-half row max (quad reduce) ----
        float rmlo = NEG_BIG, rmhi = NEG_BIG;
#pragma unroll
        for (int nf = 0; nf < 4; nf++) {
            rmlo = fmaxf(rmlo, fmaxf(acc[nf][0], acc[nf][1]));
            rmhi = fmaxf(rmhi, fmaxf(acc[nf][2], acc[nf][3]));
        }
#pragma unroll
        for (int off = 1; off < 4; off <<= 1) {
            rmlo = fmaxf(rmlo, __shfl_xor_sync(0xffffffffu, rmlo, off));
            rmhi = fmaxf(rmhi, __shfl_xor_sync(0xffffffffu, rmhi, off));
        }
        if (lr == 0) { smax[nh * 128 + rlo] = rmlo; smax[nh * 128 + rhi] = rmhi; }
        __syncthreads();   // [bar1] cross-half max visible

        rmlo = fmaxf(rmlo, smax[(nh ^ 1) * 128 + rlo]);
        rmhi = fmaxf(rmhi, smax[(nh ^ 1) * 128 + rhi]);
        const float nmlo = fmaxf(mlo, rmlo), nmhi = fmaxf(mhi, rmhi);
        const float alo = __expf(mlo - nmlo), ahi = __expf(mhi - nmhi);

        // ---- exp + P store + partial sums ----
        float slo = 0.0f, shi = 0.0f;
        u32* PsU = (u32*)Ps;
#pragma unroll
        for (int nf = 0; nf < 4; nf++) {
            float p0 = __expf(acc[nf][0] - nmlo);
            float p1 = __expf(acc[nf][1] - nmlo);
            float p2 = __expf(acc[nf][2] - nmhi);
            float p3 = __expf(acc[nf][3] - nmhi);
            slo += p0 + p1; shi += p2 + p3;
            const int nb = (nh * 4 + nf) * 8;
            PsU[rlo * PS_STR + nb + g0] = tf32_rna(p0);
            PsU[rlo * PS_STR + nb + g1] = tf32_rna(p1);
            PsU[rhi * PS_STR + nb + g0] = tf32_rna(p2);
            PsU[rhi * PS_STR + nb + g1] = tf32_rna(p3);
        }
#pragma unroll
        for (int off = 1; off < 4; off <<= 1) {
            slo += __shfl_xor_sync(0xffffffffu, slo, off);
            shi += __shfl_xor_sync(0xffffffffu, shi, off);
        }
        if (lr == 0) { ssum[nh * 128 + rlo] = slo; ssum[nh * 128 + rhi] = shi; }
        __syncthreads();   // [bar2] P + sums visible

        llo = llo * alo + slo + ssum[(nh ^ 1) * 128 + rlo];
        lhi = lhi * ahi + shi + ssum[(nh ^ 1) * 128 + rhi];
        mlo = nmlo; mhi = nmhi;

        // ---- O rescale + AV: m16 x n64 (warp's h-half) ----
#pragma unroll
        for (int nf = 0; nf < 8; nf++) {
            O[nf][0] *= alo; O[nf][1] *= alo;
            O[nf][2] *= ahi; O[nf][3] *= ahi;
        }
        const u32* pal = (const u32*)Ps + rlo * PS_STR + 2 * lr;
        const u32* pah = (const u32*)Ps + rhi * PS_STR + 2 * lr;
        const u32* vb  = (const u32*)Vc + lq * VS_STR + 2 * lr;
#pragma unroll 2
        for (int ks = 0; ks < 8; ks++) {
            const int ko = ks * 8;
            u32 a0, a1, a2, a3;
            unpk(*(const u64*)(pal + ko), a0, a2);
            unpk(*(const u64*)(pah + ko), a1, a3);
#pragma unroll
            for (int nf = 0; nf < 8; nf++) {
                u32 b0, b1;
                unpk(*(const u64*)(vb + (nh * 8 + nf) * (8 * VS_STR) + ko), b0, b1);
                mma_tf32(O[nf], a0, a1, a2, a3, b0, b1);
            }
        }

        if (kt + 1 < kt1) CP_WAIT0();
        __syncthreads();   // [bar3] stage + Ps + red reuse safe
    }
#undef LOAD_TILE

    // ---- write partials: rows rlo/rhi, h-half nh ----
    const size_t base = (size_t)(z * BATCH + b) * SEQ + q0;
    float* oplo = g_part + (base + rlo) * HEAD + 64 * nh + 2 * lr;
    float* ophi = g_part + (base + rhi) * HEAD + 64 * nh + 2 * lr;
#pragma unroll
    for (int nf = 0; nf < 8; nf++) {
        *(u64*)(oplo + nf * 8) = pack2(O[nf][0], O[nf][1]);
        *(u64*)(ophi + nf * 8) = pack2(O[nf][2], O[nf][3]);
    }
    if (nh == 0 && lr == 0) {
        g_mp[base + rlo] = mlo; g_lp[base + rlo] = llo;
        g_mp[base + rhi] = mhi; g_lp[base + rhi] = lhi;
    }
}

// ============================================================================
// Kernel 3: merge split-K partials
// ============================================================================
__global__ __launch_bounds__(256) void combine_kernel(float* __restrict__ out)
{
    const int idx = blockIdx.x * 256 + threadIdx.x;
    const int row = idx >> 5, h4 = idx & 31;
    const float m0 = g_mp[row], m1 = g_mp[ROWS_TOTAL + row];
    const float l0 = g_lp[row], l1 = g_lp[ROWS_TOTAL + row];
    const float mm = fmaxf(m0, m1);
    const float a0 = __expf(m0 - mm), a1 = __expf(m1 - mm);
    const float inv = 1.0f / (l0 * a0 + l1 * a1);
    const float4 o0 = *(const float4*)(g_part + (size_t)row * HEAD + h4 * 4);
    const float4 o1 = *(const float4*)(g_part + ((size_t)ROWS_TOTAL + row) * HEAD + h4 * 4);
    float4 r;
    r.x = (o0.x * a0 + o1.x * a1) * inv;
    r.y = (o0.y * a0 + o1.y * a1) * inv;
    r.z = (o0.z * a0 + o1.z * a1) * inv;
    r.w = (o0.w * a0 + o1.w * a1) * inv;
    *(float4*)(out + (size_t)row * HEAD + h4 * 4) = r;
}

// ============================================================================
extern "C" void kernel_launch(void* const* d_in, const int* in_sizes, int n_in,
                              void* d_out, int out_size)
{
    const float* x  = (const float*)d_in[0];
    const float* Wq = (const float*)d_in[1];
    const float* Wk = (const float*)d_in[2];
    const float* Wv = (const float*)d_in[3];
    float* out = (float*)d_out;

    (void)cudaFuncSetAttribute(qkv_mma_kernel,
        cudaFuncAttributeMaxDynamicSharedMemorySize, QKV_SMEM);
    dim3 qgrid(ROWS_TOTAL / BM, 3);
    qkv_mma_kernel<<<qgrid, 256, QKV_SMEM>>>(x, Wq, Wk, Wv);

    (void)cudaFuncSetAttribute(attn_kernel,
        cudaFuncAttributeMaxDynamicSharedMemorySize, ATT_SMEM);
    attn_kernel<<<256, 512, ATT_SMEM>>>();

    combine_kernel<<<(ROWS_TOTAL * 32) / 256, 256>>>(out);
}

// round 15
// speedup vs baseline: 1.0134x; 1.0134x over previous
#include <cuda_runtime.h>
#include <cstdint>

#define EMBED 1024
#define HEAD  128
#define SEQ   4096
#define BATCH 4
#define ROWS_TOTAL (BATCH*SEQ)

typedef unsigned long long u64;
typedef unsigned int u32;

// scratch (device globals; no allocations allowed)
static __device__ float g_q [(size_t)ROWS_TOTAL * HEAD];    // fp32, [b][s][h'] h-interleaved
static __device__ float g_k [(size_t)ROWS_TOTAL * HEAD];    // tf32 BITS, [b][s][h'] h-interleaved
static __device__ float g_vT[(size_t)BATCH * HEAD * SEQ];   // tf32 BITS, [b][h][s'] s-interleaved
static __device__ float g_part[(size_t)2 * ROWS_TOTAL * HEAD];
static __device__ float g_mp[2 * ROWS_TOTAL];
static __device__ float g_lp[2 * ROWS_TOTAL];

__device__ __forceinline__ u64 pack2(float lo, float hi) {
    u64 r; asm("mov.b64 %0, {%1, %2};" : "=l"(r) : "f"(lo), "f"(hi)); return r;
}
__device__ __forceinline__ void unpk(u64 v, u32& lo, u32& hi) {
    asm("mov.b64 {%0, %1}, %2;" : "=r"(lo), "=r"(hi) : "l"(v));
}
__device__ __forceinline__ u32 tf32_rna(float f) {
    u32 r; asm("cvt.rna.tf32.f32 %0, %1;" : "=r"(r) : "f"(f)); return r;
}
__device__ __forceinline__ int p8(int j) { return (j < 4) ? (j << 1) : (((j - 4) << 1) | 1); }
__device__ __forceinline__ u32 smem_u32(const void* p) {
    u32 a; asm("{ .reg .u64 t; cvta.to.shared.u64 t, %1; cvt.u32.u64 %0, t; }" : "=r"(a) : "l"(p));
    return a;
}
#define CP16(dst_u32, src_ptr) \
    asm volatile("cp.async.cg.shared.global [%0], [%1], 16;" :: "r"(dst_u32), "l"(src_ptr))
#define CP_COMMIT() asm volatile("cp.async.commit_group;" ::: "memory")
#define CP_WAIT0()  asm volatile("cp.async.wait_group 0;" ::: "memory")

__device__ __forceinline__ void mma_tf32(float* d, u32 a0, u32 a1, u32 a2, u32 a3,
                                         u32 b0, u32 b1) {
    asm volatile("mma.sync.aligned.m16n8k8.row.col.f32.tf32.tf32.f32 "
        "{%0,%1,%2,%3}, {%4,%5,%6,%7}, {%8,%9}, {%0,%1,%2,%3};"
        : "+f"(d[0]), "+f"(d[1]), "+f"(d[2]), "+f"(d[3])
        : "r"(a0), "r"(a1), "r"(a2), "r"(a3), "r"(b0), "r"(b1));
}

// ============================================================================
// Kernel 1: QKV via mma.sync tf32 — NOW 512 threads / 16 warps (4/SMSP).
// Warp grid: 8 in m x 2 in n; warp tile m16 x n64 (acc 32 regs).
// Same smem layouts/strides as the proven R6 kernel; same K-accumulation
// order per output element -> bit-identical results expected.
// ============================================================================
#define BM 128
#define BK 32
#define NCH (EMBED / BK)
#define AS_STR 36
#define BS_STR 136
#define AS_SZ (BM * AS_STR)
#define BS_SZ (BK * BS_STR)
#define QKV_SMEM ((AS_SZ + BS_SZ) * 2 * 4)

__global__ __launch_bounds__(512, 1) void qkv_mma_kernel(
    const float* __restrict__ x, const float* __restrict__ Wq,
    const float* __restrict__ Wk, const float* __restrict__ Wv)
{
    extern __shared__ __align__(16) float smq[];
    const int tid  = threadIdx.x;
    const int lane = tid & 31;
    const int wid  = tid >> 5;                 // 0..15
    const int warp_m = (wid & 7) * 16;         // 8 warps in m
    const int warp_n = (wid >> 3) * 64;        // 2 warps in n
    const int m0 = blockIdx.x * BM;
    const int w  = blockIdx.y;
    const float* W = (w == 0) ? Wq : (w == 1) ? Wk : Wv;

    const int lq = lane >> 2;                  // 0..7
    const int lr = lane & 3;                   // 0..3

    float* Asb[2] = { smq,         smq + AS_SZ + BS_SZ };
    float* Bsb[2] = { smq + AS_SZ, smq + 2 * AS_SZ + BS_SZ };

    float4 areg[2], breg[2];

#define LDG_CHUNK(c) do { \
    _Pragma("unroll") \
    for (int i = 0; i < 2; i++) { \
        int idx = tid + i * 512; \
        int row = idx >> 3, kq = idx & 7; \
        areg[i] = *(const float4*)(x + (size_t)(m0 + row) * EMBED + (c) * BK + kq * 4); \
        int k = idx >> 5, nq = idx & 31; \
        breg[i] = *(const float4*)(W + (size_t)((c) * BK + k) * HEAD + nq * 4); \
    } \
} while (0)

#define STS_CHUNK(buf) do { \
    _Pragma("unroll") \
    for (int i = 0; i < 2; i++) { \
        int idx = tid + i * 512; \
        int row = idx >> 3, kq = idx & 7; \
        uint4 av = { tf32_rna(areg[i].x), tf32_rna(areg[i].y), \
                     tf32_rna(areg[i].z), tf32_rna(areg[i].w) }; \
        *(uint4*)(Asb[buf] + row * AS_STR + kq * 4) = av; \
        int k = idx >> 5, nq = idx & 31; \
        uint4 bv = { tf32_rna(breg[i].x), tf32_rna(breg[i].y), \
                     tf32_rna(breg[i].z), tf32_rna(breg[i].w) }; \
        *(uint4*)(Bsb[buf] + k * BS_STR + nq * 4) = bv; \
    } \
} while (0)

    float acc[8][4];
#pragma unroll
    for (int nf = 0; nf < 8; nf++)
#pragma unroll
        for (int i = 0; i < 4; i++) acc[nf][i] = 0.0f;

    LDG_CHUNK(0);
    STS_CHUNK(0);
    __syncthreads();

    for (int c = 0; c < NCH; c++) {
        const int buf = c & 1;
        if (c + 1 < NCH) LDG_CHUNK(c + 1);

        const u32* ap = (const u32*)Asb[buf] + (warp_m + lq) * AS_STR + lr;
        const u32* bp = (const u32*)Bsb[buf] + lr * BS_STR + warp_n + lq;
#pragma unroll
        for (int ks = 0; ks < 4; ks++) {
            const int o = ks * 8;
            u32 a0 = ap[o];
            u32 a1 = ap[o + 8 * AS_STR];
            u32 a2 = ap[o + 4];
            u32 a3 = ap[o + 8 * AS_STR + 4];
#pragma unroll
            for (int nf = 0; nf < 8; nf++) {
                const int ob = ks * (8 * BS_STR) + nf * 8;
                mma_tf32(acc[nf], a0, a1, a2, a3, bp[ob], bp[ob + 4 * BS_STR]);
            }
        }

        if (c + 1 < NCH) {
            STS_CHUNK((c + 1) & 1);
            __syncthreads();
        }
    }

    // ---- epilogue: same storage formats as before (attn depends on them) ----
    const int g0 = p8(2 * lr), g1 = p8(2 * lr + 1);
    const int mrow = m0 + warp_m + lq;         // second row = mrow + 8
#pragma unroll
    for (int nf = 0; nf < 8; nf++) {
        const int nbase = warp_n + nf * 8;
        if (w == 2) {   // V -> g_vT[b][h][s'] as tf32 bits (s-interleaved)
            const int b0 = mrow >> 12, rb = mrow & (SEQ - 1);
            const int rbp = (rb & ~7) | p8(rb & 7);
            u32* vp = (u32*)(g_vT + ((size_t)b0 * HEAD + nbase + 2 * lr) * SEQ + rbp);
            vp[0]       = tf32_rna(acc[nf][0]);
            vp[SEQ]     = tf32_rna(acc[nf][1]);
            vp[8]       = tf32_rna(acc[nf][2]);
            vp[SEQ + 8] = tf32_rna(acc[nf][3]);
        } else if (w == 1) {  // K -> g_k as tf32 bits, h-interleaved
            u32* p0 = (u32*)(g_k + (size_t)mrow * HEAD + nbase);
            p0[g0]            = tf32_rna(acc[nf][0]);
            p0[g1]            = tf32_rna(acc[nf][1]);
            p0[g0 + 8 * HEAD] = tf32_rna(acc[nf][2]);
            p0[g1 + 8 * HEAD] = tf32_rna(acc[nf][3]);
        } else {              // Q fp32, h-interleaved
            float* p0 = g_q + (size_t)mrow * HEAD + nbase;
            p0[g0]            = acc[nf][0];
            p0[g1]            = acc[nf][1];
            p0[g0 + 8 * HEAD] = acc[nf][2];
            p0[g1 + 8 * HEAD] = acc[nf][3];
        }
    }
#undef LDG_CHUNK
#undef STS_CHUNK
}

// ============================================================================
// Kernel 2: flash attention — byte-identical to the R13 passing version.
// 256 thr, 8 warps; Q frags in regs; K/V cp.async double-buffered.
// ============================================================================
#define NEG_BIG (-3.0e38f)
#define M_INIT  (-1.0e30f)
#define QT_STR 136
#define KS_STR 136
#define VS_STR 72
#define PS_STR 72
#define KS_SZ (64 * KS_STR)
#define VS_SZ (128 * VS_STR)
#define PS_SZ (128 * PS_STR)
#define ATT_SMEM ((2 * (KS_SZ + VS_SZ) + PS_SZ) * 4)   // 180224 B

__global__ __launch_bounds__(256, 1) void attn_kernel()
{
    extern __shared__ __align__(16) float smf[];
    float* Ks0 = smf;
    float* Vs0 = Ks0 + KS_SZ;
    float* Ks1 = Vs0 + VS_SZ;
    float* Vs1 = Ks1 + KS_SZ;
    float* Ps  = Vs1 + VS_SZ;
    float* Qtmp = Ks1;               // transient Q staging

    const int tid  = threadIdx.x;
    const int lane = tid & 31;
    const int w    = tid >> 5;
    const int id = blockIdx.x;
    const int qt = 31 - (id >> 3);
    const int z  = id & 1;
    const int b  = (id >> 1) & 3;
    const int q0 = qt * 128;
    const float scale = 0.08838834764831845f;

    const int lq = lane >> 2;
    const int lr = lane & 3;
    const int rlo = w * 16 + lq, rhi = rlo + 8;
    const int g0 = p8(2 * lr), g1 = p8(2 * lr + 1);

    // ---- stage Q (scaled + rna) into transient smem, extract frags ----
    {
        const float* qg = g_q + ((size_t)b * SEQ + q0) * HEAD;
#pragma unroll
        for (int i = 0; i < 16; i++) {
            int idx = tid + i * 256;
            int h4 = idx >> 7, r = idx & 127;
            float4 v = *(const float4*)(qg + (size_t)r * HEAD + h4 * 4);
            uint4 t = { tf32_rna(v.x * scale), tf32_rna(v.y * scale),
                        tf32_rna(v.z * scale), tf32_rna(v.w * scale) };
            *(uint4*)(Qtmp + r * QT_STR + h4 * 4) = t;
        }
    }
    __syncthreads();
    u32 qa[16][4];
    {
        const u32* apl = (const u32*)Qtmp + rlo * QT_STR + 2 * lr;
        const u32* aph = (const u32*)Qtmp + rhi * QT_STR + 2 * lr;
#pragma unroll
        for (int ks = 0; ks < 16; ks++) {
            unpk(*(const u64*)(apl + ks * 8), qa[ks][0], qa[ks][2]);
            unpk(*(const u64*)(aph + ks * 8), qa[ks][1], qa[ks][3]);
        }
    }
    __syncthreads();

#define LOAD_TILE(ktv, Kd, Vd) do { \
    const float* kg = g_k + ((size_t)b * SEQ + (size_t)(ktv) * 64) * HEAD; \
    const float* vg = g_vT + (size_t)b * HEAD * SEQ + (size_t)(ktv) * 64; \
    _Pragma("unroll") \
    for (int i = 0; i < 8; i++) { \
        int idx = tid + i * 256; \
        int e4 = idx & 31, r = idx >> 5; \
        CP16(smem_u32((Kd) + r * KS_STR + e4 * 4), kg + (size_t)r * HEAD + e4 * 4); \
        int h = idx >> 4, k4 = idx & 15; \
        CP16(smem_u32((Vd) + h * VS_STR + k4 * 4), vg + (size_t)h * SEQ + k4 * 4); \
    } \
} while (0)

    float O[16][4];
#pragma unroll
    for (int nf = 0; nf < 16; nf++)
#pragma unroll
        for (int i = 0; i < 4; i++) O[nf][i] = 0.0f;
    float mlo = M_INIT, mhi = M_INIT, llo = 0.0f, lhi = 0.0f;

    const int kt0 = z ? (qt + 1) : 0;
    const int kt1 = z ? (2 * qt + 2) : (qt + 1);

    LOAD_TILE(kt0, Ks0, Vs0);
    CP_COMMIT();
    CP_WAIT0();
    __syncthreads();

    for (int kt = kt0; kt < kt1; kt++) {
        const int st = (kt - kt0) & 1;
        float* Kc = st ? Ks1 : Ks0;
        float* Vc = st ? Vs1 : Vs0;

        if (kt + 1 < kt1) {
            LOAD_TILE(kt + 1, st ? Ks0 : Ks1, st ? Vs0 : Vs1);
            CP_COMMIT();
        }

        // ---- scores: warp m16 x n64, Q in regs ----
        float acc[8][4];
#pragma unroll
        for (int nf = 0; nf < 8; nf++)
#pragma unroll
            for (int i = 0; i < 4; i++) acc[nf][i] = 0.0f;

        const u32* bp = (const u32*)Kc + lq * KS_STR + 2 * lr;
#pragma unroll 2
        for (int ks = 0; ks < 16; ks++) {
            const int ko = ks * 8;
#pragma unroll
            for (int nf = 0; nf < 8; nf++) {
                u32 b0, b1;
                unpk(*(const u64*)(bp + nf * (8 * KS_STR) + ko), b0, b1);
                mma_tf32(acc[nf], qa[ks][0], qa[ks][1], qa[ks][2], qa[ks][3], b0, b1);
            }
        }

        if (kt >= 2 * qt) {
            const int koff = (kt - 2 * qt) * 64;
#pragma unroll
            for (int nf = 0; nf < 8; nf++) {
                const int c0 = koff + nf * 8 + 2 * lr;
                if (c0 > rlo)     acc[nf][0] = NEG_BIG;
                if (c0 + 1 > rlo) acc[nf][1] = NEG_BIG;
                if (c0 > rhi)     acc[nf][2] = NEG_BIG;
                if (c0 + 1 > rhi) acc[nf][3] = NEG_BIG;
            }
        }

        // ---- online softmax (quad reduction) ----
        float rmlo = NEG_BIG, rmhi = NEG_BIG;
#pragma unroll
        for (int nf = 0; nf < 8; nf++) {
            rmlo = fmaxf(rmlo, fmaxf(acc[nf][0], acc[nf][1]));
            rmhi = fmaxf(rmhi, fmaxf(acc[nf][2], acc[nf][3]));
        }
#pragma unroll
        for (int off = 1; off < 4; off <<= 1) {
            rmlo = fmaxf(rmlo, __shfl_xor_sync(0xffffffffu, rmlo, off));
            rmhi = fmaxf(rmhi, __shfl_xor_sync(0xffffffffu, rmhi, off));
        }
        const float nmlo = fmaxf(mlo, rmlo), nmhi = fmaxf(mhi, rmhi);
        const float alo = __expf(mlo - nmlo), ahi = __expf(mhi - nmhi);
        float slo = 0.0f, shi = 0.0f;
        u32* PsU = (u32*)Ps;
#pragma unroll
        for (int nf = 0; nf < 8; nf++) {
            float p0 = __expf(acc[nf][0] - nmlo);
            float p1 = __expf(acc[nf][1] - nmlo);
            float p2 = __expf(acc[nf][2] - nmhi);
            float p3 = __expf(acc[nf][3] - nmhi);
            slo += p0 + p1; shi += p2 + p3;
            PsU[rlo * PS_STR + nf * 8 + g0] = tf32_rna(p0);
            PsU[rlo * PS_STR + nf * 8 + g1] = tf32_rna(p1);
            PsU[rhi * PS_STR + nf * 8 + g0] = tf32_rna(p2);
            PsU[rhi * PS_STR + nf * 8 + g1] = tf32_rna(p3);
        }
#pragma unroll
        for (int off = 1; off < 4; off <<= 1) {
            slo += __shfl_xor_sync(0xffffffffu, slo, off);
            shi += __shfl_xor_sync(0xffffffffu, shi, off);
        }
        llo = llo * alo + slo; mlo = nmlo;
        lhi = lhi * ahi + shi; mhi = nmhi;
        __syncwarp();

        // ---- O rescale + AV: warp m16 x n128 ----
#pragma unroll
        for (int nf = 0; nf < 16; nf++) {
            O[nf][0] *= alo; O[nf][1] *= alo;
            O[nf][2] *= ahi; O[nf][3] *= ahi;
        }
        const u32* pal = (const u32*)Ps + rlo * PS_STR + 2 * lr;
        const u32* pah = (const u32*)Ps + rhi * PS_STR + 2 * lr;
        const u32* vb  = (const u32*)Vc + lq * VS_STR + 2 * lr;
#pragma unroll 2
        for (int ks = 0; ks < 8; ks++) {
            const int ko = ks * 8;
            u32 a0, a1, a2, a3;
            unpk(*(const u64*)(pal + ko), a0, a2);
            unpk(*(const u64*)(pah + ko), a1, a3);
#pragma unroll
            for (int nf = 0; nf < 16; nf++) {
                u32 b0, b1;
                unpk(*(const u64*)(vb + nf * (8 * VS_STR) + ko), b0, b1);
                mma_tf32(O[nf], a0, a1, a2, a3, b0, b1);
            }
        }

        if (kt + 1 < kt1) CP_WAIT0();
        __syncthreads();
    }
#undef LOAD_TILE

    // ---- write partials ----
    const size_t base = (size_t)(z * BATCH + b) * SEQ + q0;
    float* oplo = g_part + (base + rlo) * HEAD + 2 * lr;
    float* ophi = g_part + (base + rhi) * HEAD + 2 * lr;
#pragma unroll
    for (int nf = 0; nf < 16; nf++) {
        *(u64*)(oplo + nf * 8) = pack2(O[nf][0], O[nf][1]);
        *(u64*)(ophi + nf * 8) = pack2(O[nf][2], O[nf][3]);
    }
    if (lr == 0) {
        g_mp[base + rlo] = mlo; g_lp[base + rlo] = llo;
        g_mp[base + rhi] = mhi; g_lp[base + rhi] = lhi;
    }
}

// ============================================================================
// Kernel 3: merge split-K partials
// ============================================================================
__global__ __launch_bounds__(256) void combine_kernel(float* __restrict__ out)
{
    const int idx = blockIdx.x * 256 + threadIdx.x;
    const int row = idx >> 5, h4 = idx & 31;
    const float m0 = g_mp[row], m1 = g_mp[ROWS_TOTAL + row];
    const float l0 = g_lp[row], l1 = g_lp[ROWS_TOTAL + row];
    const float mm = fmaxf(m0, m1);
    const float a0 = __expf(m0 - mm), a1 = __expf(m1 - mm);
    const float inv = 1.0f / (l0 * a0 + l1 * a1);
    const float4 o0 = *(const float4*)(g_part + (size_t)row * HEAD + h4 * 4);
    const float4 o1 = *(const float4*)(g_part + ((size_t)ROWS_TOTAL + row) * HEAD + h4 * 4);
    float4 r;
    r.x = (o0.x * a0 + o1.x * a1) * inv;
    r.y = (o0.y * a0 + o1.y * a1) * inv;
    r.z = (o0.z * a0 + o1.z * a1) * inv;
    r.w = (o0.w * a0 + o1.w * a1) * inv;
    *(float4*)(out + (size_t)row * HEAD + h4 * 4) = r;
}

// ============================================================================
extern "C" void kernel_launch(void* const* d_in, const int* in_sizes, int n_in,
                              void* d_out, int out_size)
{
    const float* x  = (const float*)d_in[0];
    const float* Wq = (const float*)d_in[1];
    const float* Wk = (const float*)d_in[2];
    const float* Wv = (const float*)d_in[3];
    float* out = (float*)d_out;

    (void)cudaFuncSetAttribute(qkv_mma_kernel,
        cudaFuncAttributeMaxDynamicSharedMemorySize, QKV_SMEM);
    dim3 qgrid(ROWS_TOTAL / BM, 3);
    qkv_mma_kernel<<<qgrid, 512, QKV_SMEM>>>(x, Wq, Wk, Wv);

    (void)cudaFuncSetAttribute(attn_kernel,
        cudaFuncAttributeMaxDynamicSharedMemorySize, ATT_SMEM);
    attn_kernel<<<256, 256, ATT_SMEM>>>();

    combine_kernel<<<(ROWS_TOTAL * 32) / 256, 256>>>(out);
}

// round 16
// speedup vs baseline: 1.0666x; 1.0526x over previous
#include <cuda_runtime.h>
#include <cstdint>

#define EMBED 1024
#define HEAD  128
#define SEQ   4096
#define BATCH 4
#define ROWS_TOTAL (BATCH*SEQ)

typedef unsigned long long u64;
typedef unsigned int u32;

// scratch (device globals; no allocations allowed)
static __device__ float g_q [(size_t)ROWS_TOTAL * HEAD];    // fp32, [b][s][h'] h-interleaved
static __device__ float g_k [(size_t)ROWS_TOTAL * HEAD];    // tf32 BITS, [b][s][h'] h-interleaved
static __device__ float g_vT[(size_t)BATCH * HEAD * SEQ];   // tf32 BITS, [b][h][s'] s-interleaved
static __device__ float g_part[(size_t)2 * ROWS_TOTAL * HEAD];
static __device__ float g_mp[2 * ROWS_TOTAL];
static __device__ float g_lp[2 * ROWS_TOTAL];

__device__ __forceinline__ u64 pack2(float lo, float hi) {
    u64 r; asm("mov.b64 %0, {%1, %2};" : "=l"(r) : "f"(lo), "f"(hi)); return r;
}
__device__ __forceinline__ void unpk(u64 v, u32& lo, u32& hi) {
    asm("mov.b64 {%0, %1}, %2;" : "=r"(lo), "=r"(hi) : "l"(v));
}
__device__ __forceinline__ u32 tf32_rna(float f) {
    u32 r; asm("cvt.rna.tf32.f32 %0, %1;" : "=r"(r) : "f"(f)); return r;
}
__device__ __forceinline__ int p8(int j) { return (j < 4) ? (j << 1) : (((j - 4) << 1) | 1); }
__device__ __forceinline__ u32 smem_u32(const void* p) {
    u32 a; asm("{ .reg .u64 t; cvta.to.shared.u64 t, %1; cvt.u32.u64 %0, t; }" : "=r"(a) : "l"(p));
    return a;
}
#define CP16(dst_u32, src_ptr) \
    asm volatile("cp.async.cg.shared.global [%0], [%1], 16;" :: "r"(dst_u32), "l"(src_ptr))
#define CP_COMMIT() asm volatile("cp.async.commit_group;" ::: "memory")
#define CP_WAIT0()  asm volatile("cp.async.wait_group 0;" ::: "memory")

__device__ __forceinline__ void mma_tf32(float* d, u32 a0, u32 a1, u32 a2, u32 a3,
                                         u32 b0, u32 b1) {
    asm volatile("mma.sync.aligned.m16n8k8.row.col.f32.tf32.tf32.f32 "
        "{%0,%1,%2,%3}, {%4,%5,%6,%7}, {%8,%9}, {%0,%1,%2,%3};"
        : "+f"(d[0]), "+f"(d[1]), "+f"(d[2]), "+f"(d[3])
        : "r"(a0), "r"(a1), "r"(a2), "r"(a3), "r"(b0), "r"(b1));
}

// ============================================================================
// Kernel 1: QKV via mma.sync tf32 — 2 CTAs/SM.
// grid (128 m-tiles, 6 = 3 weights x 2 n-halves). BM=128, BN=64, BK=32.
// 256 thr, 8 warps (4m x 2n), warp tile m32 x n32 (acc 32 regs, <=128 total).
// Same per-output K-accumulation order as proven R6 -> bit-identical results.
// ============================================================================
#define BM 128
#define BK 32
#define NCH (EMBED / BK)
#define AS_STR 36
#define BSQ_STR 72
#define AS_SZ (BM * AS_STR)                 // 4608 floats
#define BSQ_SZ (BK * BSQ_STR)               // 2304 floats
#define QKV_SMEM ((AS_SZ + BSQ_SZ) * 2 * 4) // 55296 B

__global__ __launch_bounds__(256, 2) void qkv_mma_kernel(
    const float* __restrict__ x, const float* __restrict__ Wq,
    const float* __restrict__ Wk, const float* __restrict__ Wv)
{
    extern __shared__ __align__(16) float smq[];
    const int tid  = threadIdx.x;
    const int lane = tid & 31;
    const int wid  = tid >> 5;                 // 0..7
    const int warp_m = (wid & 3) * 32;         // 4 warps in m
    const int warp_n = (wid >> 2) * 32;        // 2 warps in n
    const int m0 = blockIdx.x * BM;
    const int w  = blockIdx.y >> 1;            // weight index
    const int n0 = (blockIdx.y & 1) * 64;      // n-half base
    const float* W = (w == 0) ? Wq : (w == 1) ? Wk : Wv;

    const int lq = lane >> 2;                  // 0..7
    const int lr = lane & 3;                   // 0..3

    float* Asb[2] = { smq,          smq + AS_SZ + BSQ_SZ };
    float* Bsb[2] = { smq + AS_SZ,  smq + 2 * AS_SZ + BSQ_SZ };

    float4 areg[4], breg[2];

#define LDG_CHUNK(c) do { \
    _Pragma("unroll") \
    for (int i = 0; i < 4; i++) { \
        int idx = tid + i * 256; \
        int row = idx >> 3, kq = idx & 7; \
        areg[i] = *(const float4*)(x + (size_t)(m0 + row) * EMBED + (c) * BK + kq * 4); \
    } \
    _Pragma("unroll") \
    for (int i = 0; i < 2; i++) { \
        int idx = tid + i * 256; \
        int k = idx >> 4, nq = idx & 15; \
        breg[i] = *(const float4*)(W + (size_t)((c) * BK + k) * HEAD + n0 + nq * 4); \
    } \
} while (0)

#define STS_CHUNK(buf) do { \
    _Pragma("unroll") \
    for (int i = 0; i < 4; i++) { \
        int idx = tid + i * 256; \
        int row = idx >> 3, kq = idx & 7; \
        uint4 av = { tf32_rna(areg[i].x), tf32_rna(areg[i].y), \
                     tf32_rna(areg[i].z), tf32_rna(areg[i].w) }; \
        *(uint4*)(Asb[buf] + row * AS_STR + kq * 4) = av; \
    } \
    _Pragma("unroll") \
    for (int i = 0; i < 2; i++) { \
        int idx = tid + i * 256; \
        int k = idx >> 4, nq = idx & 15; \
        uint4 bv = { tf32_rna(breg[i].x), tf32_rna(breg[i].y), \
                     tf32_rna(breg[i].z), tf32_rna(breg[i].w) }; \
        *(uint4*)(Bsb[buf] + k * BSQ_STR + nq * 4) = bv; \
    } \
} while (0)

    float acc[2][4][4];
#pragma unroll
    for (int mf = 0; mf < 2; mf++)
#pragma unroll
        for (int nf = 0; nf < 4; nf++)
#pragma unroll
            for (int i = 0; i < 4; i++) acc[mf][nf][i] = 0.0f;

    LDG_CHUNK(0);
    STS_CHUNK(0);
    __syncthreads();

    for (int c = 0; c < NCH; c++) {
        const int buf = c & 1;
        if (c + 1 < NCH) LDG_CHUNK(c + 1);

        const u32* ap = (const u32*)Asb[buf] + (warp_m + lq) * AS_STR + lr;
        const u32* bp = (const u32*)Bsb[buf] + lr * BSQ_STR + warp_n + lq;
#pragma unroll
        for (int ks = 0; ks < 4; ks++) {
            const int o = ks * 8;
            u32 a[2][4];
#pragma unroll
            for (int mf = 0; mf < 2; mf++) {
                const int om = mf * (16 * AS_STR) + o;
                a[mf][0] = ap[om];
                a[mf][1] = ap[om + 8 * AS_STR];
                a[mf][2] = ap[om + 4];
                a[mf][3] = ap[om + 8 * AS_STR + 4];
            }
#pragma unroll
            for (int nf = 0; nf < 4; nf++) {
                const int ob = ks * (8 * BSQ_STR) + nf * 8;
                u32 b0 = bp[ob], b1 = bp[ob + 4 * BSQ_STR];
#pragma unroll
                for (int mf = 0; mf < 2; mf++)
                    mma_tf32(acc[mf][nf], a[mf][0], a[mf][1], a[mf][2], a[mf][3], b0, b1);
            }
        }

        if (c + 1 < NCH) {
            STS_CHUNK((c + 1) & 1);
            __syncthreads();
        }
    }

    // ---- epilogue: same storage formats as before (attn depends on them) ----
    const int g0 = p8(2 * lr), g1 = p8(2 * lr + 1);
#pragma unroll
    for (int mf = 0; mf < 2; mf++) {
        const int mrow = m0 + warp_m + mf * 16 + lq;   // second row = +8
#pragma unroll
        for (int nf = 0; nf < 4; nf++) {
            const int nbase = n0 + warp_n + nf * 8;
            if (w == 2) {   // V -> g_vT[b][h][s'] as tf32 bits (s-interleaved)
                const int b0 = mrow >> 12, rb = mrow & (SEQ - 1);
                const int rbp = (rb & ~7) | p8(rb & 7);
                u32* vp = (u32*)(g_vT + ((size_t)b0 * HEAD + nbase + 2 * lr) * SEQ + rbp);
                vp[0]       = tf32_rna(acc[mf][nf][0]);
                vp[SEQ]     = tf32_rna(acc[mf][nf][1]);
                vp[8]       = tf32_rna(acc[mf][nf][2]);
                vp[SEQ + 8] = tf32_rna(acc[mf][nf][3]);
            } else if (w == 1) {  // K -> g_k as tf32 bits, h-interleaved
                u32* p0 = (u32*)(g_k + (size_t)mrow * HEAD + nbase);
                p0[g0]            = tf32_rna(acc[mf][nf][0]);
                p0[g1]            = tf32_rna(acc[mf][nf][1]);
                p0[g0 + 8 * HEAD] = tf32_rna(acc[mf][nf][2]);
                p0[g1 + 8 * HEAD] = tf32_rna(acc[mf][nf][3]);
            } else {              // Q fp32, h-interleaved
                float* p0 = g_q + (size_t)mrow * HEAD + nbase;
                p0[g0]            = acc[mf][nf][0];
                p0[g1]            = acc[mf][nf][1];
                p0[g0 + 8 * HEAD] = acc[mf][nf][2];
                p0[g1 + 8 * HEAD] = acc[mf][nf][3];
            }
        }
    }
#undef LDG_CHUNK
#undef STS_CHUNK
}

// ============================================================================
// Kernel 2: flash attention — byte-identical to the R13 passing version.
// ============================================================================
#define NEG_BIG (-3.0e38f)
#define M_INIT  (-1.0e30f)
#define QT_STR 136
#define KS_STR 136
#define VS_STR 72
#define PS_STR 72
#define KS_SZ (64 * KS_STR)
#define VS_SZ (128 * VS_STR)
#define PS_SZ (128 * PS_STR)
#define ATT_SMEM ((2 * (KS_SZ + VS_SZ) + PS_SZ) * 4)   // 180224 B

__global__ __launch_bounds__(256, 1) void attn_kernel()
{
    extern __shared__ __align__(16) float smf[];
    float* Ks0 = smf;
    float* Vs0 = Ks0 + KS_SZ;
    float* Ks1 = Vs0 + VS_SZ;
    float* Vs1 = Ks1 + KS_SZ;
    float* Ps  = Vs1 + VS_SZ;
    float* Qtmp = Ks1;               // transient Q staging

    const int tid  = threadIdx.x;
    const int lane = tid & 31;
    const int w    = tid >> 5;
    const int id = blockIdx.x;
    const int qt = 31 - (id >> 3);
    const int z  = id & 1;
    const int b  = (id >> 1) & 3;
    const int q0 = qt * 128;
    const float scale = 0.08838834764831845f;

    const int lq = lane >> 2;
    const int lr = lane & 3;
    const int rlo = w * 16 + lq, rhi = rlo + 8;
    const int g0 = p8(2 * lr), g1 = p8(2 * lr + 1);

    // ---- stage Q (scaled + rna) into transient smem, extract frags ----
    {
        const float* qg = g_q + ((size_t)b * SEQ + q0) * HEAD;
#pragma unroll
        for (int i = 0; i < 16; i++) {
            int idx = tid + i * 256;
            int h4 = idx >> 7, r = idx & 127;
            float4 v = *(const float4*)(qg + (size_t)r * HEAD + h4 * 4);
            uint4 t = { tf32_rna(v.x * scale), tf32_rna(v.y * scale),
                        tf32_rna(v.z * scale), tf32_rna(v.w * scale) };
            *(uint4*)(Qtmp + r * QT_STR + h4 * 4) = t;
        }
    }
    __syncthreads();
    u32 qa[16][4];
    {
        const u32* apl = (const u32*)Qtmp + rlo * QT_STR + 2 * lr;
        const u32* aph = (const u32*)Qtmp + rhi * QT_STR + 2 * lr;
#pragma unroll
        for (int ks = 0; ks < 16; ks++) {
            unpk(*(const u64*)(apl + ks * 8), qa[ks][0], qa[ks][2]);
            unpk(*(const u64*)(aph + ks * 8), qa[ks][1], qa[ks][3]);
        }
    }
    __syncthreads();

#define LOAD_TILE(ktv, Kd, Vd) do { \
    const float* kg = g_k + ((size_t)b * SEQ + (size_t)(ktv) * 64) * HEAD; \
    const float* vg = g_vT + (size_t)b * HEAD * SEQ + (size_t)(ktv) * 64; \
    _Pragma("unroll") \
    for (int i = 0; i < 8; i++) { \
        int idx = tid + i * 256; \
        int e4 = idx & 31, r = idx >> 5; \
        CP16(smem_u32((Kd) + r * KS_STR + e4 * 4), kg + (size_t)r * HEAD + e4 * 4); \
        int h = idx >> 4, k4 = idx & 15; \
        CP16(smem_u32((Vd) + h * VS_STR + k4 * 4), vg + (size_t)h * SEQ + k4 * 4); \
    } \
} while (0)

    float O[16][4];
#pragma unroll
    for (int nf = 0; nf < 16; nf++)
#pragma unroll
        for (int i = 0; i < 4; i++) O[nf][i] = 0.0f;
    float mlo = M_INIT, mhi = M_INIT, llo = 0.0f, lhi = 0.0f;

    const int kt0 = z ? (qt + 1) : 0;
    const int kt1 = z ? (2 * qt + 2) : (qt + 1);

    LOAD_TILE(kt0, Ks0, Vs0);
    CP_COMMIT();
    CP_WAIT0();
    __syncthreads();

    for (int kt = kt0; kt < kt1; kt++) {
        const int st = (kt - kt0) & 1;
        float* Kc = st ? Ks1 : Ks0;
        float* Vc = st ? Vs1 : Vs0;

        if (kt + 1 < kt1) {
            LOAD_TILE(kt + 1, st ? Ks0 : Ks1, st ? Vs0 : Vs1);
            CP_COMMIT();
        }

        // ---- scores: warp m16 x n64, Q in regs ----
        float acc[8][4];
#pragma unroll
        for (int nf = 0; nf < 8; nf++)
#pragma unroll
            for (int i = 0; i < 4; i++) acc[nf][i] = 0.0f;

        const u32* bp = (const u32*)Kc + lq * KS_STR + 2 * lr;
#pragma unroll 2
        for (int ks = 0; ks < 16; ks++) {
            const int ko = ks * 8;
#pragma unroll
            for (int nf = 0; nf < 8; nf++) {
                u32 b0, b1;
                unpk(*(const u64*)(bp + nf * (8 * KS_STR) + ko), b0, b1);
                mma_tf32(acc[nf], qa[ks][0], qa[ks][1], qa[ks][2], qa[ks][3], b0, b1);
            }
        }

        if (kt >= 2 * qt) {
            const int koff = (kt - 2 * qt) * 64;
#pragma unroll
            for (int nf = 0; nf < 8; nf++) {
                const int c0 = koff + nf * 8 + 2 * lr;
                if (c0 > rlo)     acc[nf][0] = NEG_BIG;
                if (c0 + 1 > rlo) acc[nf][1] = NEG_BIG;
                if (c0 > rhi)     acc[nf][2] = NEG_BIG;
                if (c0 + 1 > rhi) acc[nf][3] = NEG_BIG;
            }
        }

        // ---- online softmax (quad reduction) ----
        float rmlo = NEG_BIG, rmhi = NEG_BIG;
#pragma unroll
        for (int nf = 0; nf < 8; nf++) {
            rmlo = fmaxf(rmlo, fmaxf(acc[nf][0], acc[nf][1]));
            rmhi = fmaxf(rmhi, fmaxf(acc[nf][2], acc[nf][3]));
        }
#pragma unroll
        for (int off = 1; off < 4; off <<= 1) {
            rmlo = fmaxf(rmlo, __shfl_xor_sync(0xffffffffu, rmlo, off));
            rmhi = fmaxf(rmhi, __shfl_xor_sync(0xffffffffu, rmhi, off));
        }
        const float nmlo = fmaxf(mlo, rmlo), nmhi = fmaxf(mhi, rmhi);
        const float alo = __expf(mlo - nmlo), ahi = __expf(mhi - nmhi);
        float slo = 0.0f, shi = 0.0f;
        u32* PsU = (u32*)Ps;
#pragma unroll
        for (int nf = 0; nf < 8; nf++) {
            float p0 = __expf(acc[nf][0] - nmlo);
            float p1 = __expf(acc[nf][1] - nmlo);
            float p2 = __expf(acc[nf][2] - nmhi);
            float p3 = __expf(acc[nf][3] - nmhi);
            slo += p0 + p1; shi += p2 + p3;
            PsU[rlo * PS_STR + nf * 8 + g0] = tf32_rna(p0);
            PsU[rlo * PS_STR + nf * 8 + g1] = tf32_rna(p1);
            PsU[rhi * PS_STR + nf * 8 + g0] = tf32_rna(p2);
            PsU[rhi * PS_STR + nf * 8 + g1] = tf32_rna(p3);
        }
#pragma unroll
        for (int off = 1; off < 4; off <<= 1) {
            slo += __shfl_xor_sync(0xffffffffu, slo, off);
            shi += __shfl_xor_sync(0xffffffffu, shi, off);
        }
        llo = llo * alo + slo; mlo = nmlo;
        lhi = lhi * ahi + shi; mhi = nmhi;
        __syncwarp();

        // ---- O rescale + AV: warp m16 x n128 ----
#pragma unroll
        for (int nf = 0; nf < 16; nf++) {
            O[nf][0] *= alo; O[nf][1] *= alo;
            O[nf][2] *= ahi; O[nf][3] *= ahi;
        }
        const u32* pal = (const u32*)Ps + rlo * PS_STR + 2 * lr;
        const u32* pah = (const u32*)Ps + rhi * PS_STR + 2 * lr;
        const u32* vb  = (const u32*)Vc + lq * VS_STR + 2 * lr;
#pragma unroll 2
        for (int ks = 0; ks < 8; ks++) {
            const int ko = ks * 8;
            u32 a0, a1, a2, a3;
            unpk(*(const u64*)(pal + ko), a0, a2);
            unpk(*(const u64*)(pah + ko), a1, a3);
#pragma unroll
            for (int nf = 0; nf < 16; nf++) {
                u32 b0, b1;
                unpk(*(const u64*)(vb + nf * (8 * VS_STR) + ko), b0, b1);
                mma_tf32(O[nf], a0, a1, a2, a3, b0, b1);
            }
        }

        if (kt + 1 < kt1) CP_WAIT0();
        __syncthreads();
    }
#undef LOAD_TILE

    // ---- write partials ----
    const size_t base = (size_t)(z * BATCH + b) * SEQ + q0;
    float* oplo = g_part + (base + rlo) * HEAD + 2 * lr;
    float* ophi = g_part + (base + rhi) * HEAD + 2 * lr;
#pragma unroll
    for (int nf = 0; nf < 16; nf++) {
        *(u64*)(oplo + nf * 8) = pack2(O[nf][0], O[nf][1]);
        *(u64*)(ophi + nf * 8) = pack2(O[nf][2], O[nf][3]);
    }
    if (lr == 0) {
        g_mp[base + rlo] = mlo; g_lp[base + rlo] = llo;
        g_mp[base + rhi] = mhi; g_lp[base + rhi] = lhi;
    }
}

// ============================================================================
// Kernel 3: merge split-K partials
// ============================================================================
__global__ __launch_bounds__(256) void combine_kernel(float* __restrict__ out)
{
    const int idx = blockIdx.x * 256 + threadIdx.x;
    const int row = idx >> 5, h4 = idx & 31;
    const float m0 = g_mp[row], m1 = g_mp[ROWS_TOTAL + row];
    const float l0 = g_lp[row], l1 = g_lp[ROWS_TOTAL + row];
    const float mm = fmaxf(m0, m1);
    const float a0 = __expf(m0 - mm), a1 = __expf(m1 - mm);
    const float inv = 1.0f / (l0 * a0 + l1 * a1);
    const float4 o0 = *(const float4*)(g_part + (size_t)row * HEAD + h4 * 4);
    const float4 o1 = *(const float4*)(g_part + ((size_t)ROWS_TOTAL + row) * HEAD + h4 * 4);
    float4 r;
    r.x = (o0.x * a0 + o1.x * a1) * inv;
    r.y = (o0.y * a0 + o1.y * a1) * inv;
    r.z = (o0.z * a0 + o1.z * a1) * inv;
    r.w = (o0.w * a0 + o1.w * a1) * inv;
    *(float4*)(out + (size_t)row * HEAD + h4 * 4) = r;
}

// ============================================================================
extern "C" void kernel_launch(void* const* d_in, const int* in_sizes, int n_in,
                              void* d_out, int out_size)
{
    const float* x  = (const float*)d_in[0];
    const float* Wq = (const float*)d_in[1];
    const float* Wk = (const float*)d_in[2];
    const float* Wv = (const float*)d_in[3];
    float* out = (float*)d_out;

    (void)cudaFuncSetAttribute(qkv_mma_kernel,
        cudaFuncAttributeMaxDynamicSharedMemorySize, QKV_SMEM);
    dim3 qgrid(ROWS_TOTAL / BM, 6);
    qkv_mma_kernel<<<qgrid, 256, QKV_SMEM>>>(x, Wq, Wk, Wv);

    (void)cudaFuncSetAttribute(attn_kernel,
        cudaFuncAttributeMaxDynamicSharedMemorySize, ATT_SMEM);
    attn_kernel<<<256, 256, ATT_SMEM>>>();

    combine_kernel<<<(ROWS_TOTAL * 32) / 256, 256>>>(out);
}